// round 6
// baseline (speedup 1.0000x reference)
#include <cuda_runtime.h>
#include <cuda_bf16.h>
#include <math.h>
#include <stdint.h>

#define N_SEQS   2048
#define SEQ_LEN  512
#define N_AA     20
#define M_MI     100
#define N_PAIRS  4950                    // 100*99/2 upper triangle
#define OUT_PSSM 0
#define OUT_CONS (SEQ_LEN * N_AA)        // 10240
#define OUT_MI   (OUT_CONS + SEQ_LEN)    // 10752
#define OUT_TOTAL (OUT_MI + SEQ_LEN * SEQ_LEN)  // 272896

// Scratch (no dynamic allocation allowed)
__device__ unsigned char g_colpack[128 * N_SEQS];    // column-major int8 msa[:, :128] (100 used)
__device__ int           g_part[4][SEQ_LEN][21];     // per-position AA count partials (no zeroing needed)

// ---------------------------------------------------------------------------
// Pack columns 0..99 into int8 column-major (coalesced reads, lane = column)
// AND zero the MI output region. grid (4, 64) x 256 = 65536 threads:
// exactly one float4 of the MI region per thread, one uint32 pack store.
// ---------------------------------------------------------------------------
__global__ __launch_bounds__(256) void pack_kernel(const int* __restrict__ msa,
                                                   float* __restrict__ out) {
    int tid = threadIdx.x, lane = tid & 31, w = tid >> 5;

    // Zero MI region (512*512 floats = 65536 float4)
    int gtid = (blockIdx.y * 4 + blockIdx.x) * 256 + tid;
    ((float4*)(out + OUT_MI))[gtid] = make_float4(0.f, 0.f, 0.f, 0.f);

    int col   = blockIdx.x * 32 + lane;          // 0..127 (reads only; packs <100)
    int rbase = blockIdx.y * 32 + w * 4;
    uint32_t p0 = 0;
#pragma unroll
    for (int s = 0; s < 4; s++)
        p0 |= (uint32_t)msa[(rbase + s) * SEQ_LEN + col] << (8 * s);
    if (col < M_MI)
        *(uint32_t*)&g_colpack[col * N_SEQS + rbase] = p0;
}

// ---------------------------------------------------------------------------
// Per-position AA counts -> 4 PARTIALS, plain stores (no atomics, no pre-zero,
// no dependency on any other kernel). grid (16, 4) x 256: CTA covers 32 cols
// x 512 rows; per-warp replica histograms -> private smem RMW.
// ---------------------------------------------------------------------------
__global__ __launch_bounds__(256) void count_kernel(const int* __restrict__ msa) {
    __shared__ int cnt[8][32][21];     // [warp][lane(col)][symbol]
    int tid = threadIdx.x, lane = tid & 31, w = tid >> 5;
    for (int v = tid; v < 8 * 32 * 21; v += 256) ((int*)cnt)[v] = 0;
    __syncthreads();

    int col   = blockIdx.x * 32 + lane;
    int rbase = blockIdx.y * 512 + w * 64;
    int* my = cnt[w][lane];
#pragma unroll 8
    for (int s = 0; s < 64; s++) {
        int c = msa[(rbase + s) * SEQ_LEN + col];   // coalesced 128B per warp
        my[c] += 1;                                  // private: plain RMW
    }
    __syncthreads();

    for (int v = tid; v < 32 * 21; v += 256) {
        int l = v / 21, c = v % 21;
        int s = 0;
#pragma unroll
        for (int ww = 0; ww < 8; ww++) s += cnt[ww][l][c];
        g_part[blockIdx.y][blockIdx.x * 32 + l][c] = s;   // plain store
    }
}

// ---------------------------------------------------------------------------
// PSSM + conservation: one warp per position (lane = amino acid); sums the
// 4 count partials.
// ---------------------------------------------------------------------------
__global__ __launch_bounds__(256) void pssm_kernel(float* __restrict__ out, const float* __restrict__ pc) {
    int gtid = blockIdx.x * blockDim.x + threadIdx.x;
    int p = gtid >> 5, lane = gtid & 31;
    if (p >= SEQ_LEN) return;

    int ct = 0;
    if (lane < 20)
        ct = g_part[0][p][lane] + g_part[1][p][lane] + g_part[2][p][lane] + g_part[3][p][lane];

    int t = ct;
#pragma unroll
    for (int off = 16; off; off >>= 1) t += __shfl_xor_sync(0xffffffffu, t, off);
    int total = t;

    float pcount = 0.01f * pc[0];
    float inv_den = 1.0f / ((float)N_SEQS + pcount * 20.0f);
    float tinv = 1.0f / fmaxf((float)total, 1.0f);

    float ent = 0.0f;
    if (lane < 20) {
        float freq = ((float)ct + pcount) * inv_den;
        out[OUT_PSSM + p * 20 + lane] = logf(freq * 20.0f + 1e-10f);
        float f = (float)ct * tinv;
        ent = -f * log2f(f + 1e-10f);
    }
#pragma unroll
    for (int off = 16; off; off >>= 1) ent += __shfl_xor_sync(0xffffffffu, ent, off);
    if (lane == 0)
        out[OUT_CONS + p] = (total > 0) ? (1.0f - ent * (1.0f / 4.321928094887362f)) : 0.0f;
}

// ---------------------------------------------------------------------------
// MI: one warp per (i<j) pair. Dual-unit histogramming WITHOUT per-event
// atomics on the main path:
//   - per 32-event batch, __match_any_sync dedups codes -> group leaders have
//     PROVABLY DISTINCT addresses within the batch -> plain predicated
//     LDS/IADD/STS into hist[] (smem crossbar). Cross-batch ordering is
//     preserved by may-alias ld/st semantics -> correct.
//   - every 4th batch (s==3) goes to the otherwise-idle smem ATOMIC unit
//     into a SEPARATE region hista[] (no RMW/atomic race on one address).
// Gap events (a==20||b==20) are predicated off at the leader step (cost ~0).
// Integer log2 LUT epilogue (no MUFU); H[c] = hist[c] + hista[c].
// ---------------------------------------------------------------------------
__global__ __launch_bounds__(256) void mi_kernel(float* __restrict__ mi_out) {
    __shared__ int   hist[8][448];     // RMW region (441 used, padded)
    __shared__ int   hista[8][448];    // ATOMS region
    __shared__ float lut[2049];        // log2(0..2048)
    __shared__ float slra[8][20];
    __shared__ float slcb[8][20];

    int tid = threadIdx.x, wid = tid >> 5, lane = tid & 31;
    for (int v = tid; v < 2049; v += 256) lut[v] = log2f((float)v);
    for (int v = tid; v < 8 * 448; v += 256) { ((int*)hist)[v] = 0; ((int*)hista)[v] = 0; }
    __syncthreads();

    int pid = blockIdx.x * 8 + wid;
    if (pid >= N_PAIRS) return;

    // Decode upper-triangle pair index -> (i, j), i < j; T(i) = i*(199-i)/2
    float dd = sqrtf(39601.0f - 8.0f * (float)pid);
    int i = (int)((199.0f - dd) * 0.5f);
    if (i < 0) i = 0;
    if (i > 98) i = 98;
    while ((((i + 1) * (199 - (i + 1))) >> 1) <= pid) ++i;
    while (((i * (199 - i)) >> 1) > pid) --i;
    int j = pid - ((i * (199 - i)) >> 1) + i + 1;

    int* h  = hist[wid];
    int* ha = hista[wid];

    const uint4* ca = (const uint4*)(g_colpack + i * N_SEQS);
    const uint4* cb = (const uint4*)(g_colpack + j * N_SEQS);
#pragma unroll
    for (int it = 0; it < 4; it++) {                // 4 x LDG.128 per operand
        uint4 va = ca[lane + 32 * it];
        uint4 vb = cb[lane + 32 * it];
        const uint32_t WA[4] = {va.x, va.y, va.z, va.w};
        const uint32_t WB[4] = {vb.x, vb.y, vb.z, vb.w};
#pragma unroll
        for (int q = 0; q < 4; q++) {
            uint32_t wa = WA[q], wb = WB[q];
#pragma unroll
            for (int s = 0; s < 4; s++) {
                int a = (wa >> (8 * s)) & 255;
                int b = (wb >> (8 * s)) & 255;
                int c = a * 21 + b;                       // 0..440, unique per (a,b)
                unsigned grp = __match_any_sync(0xffffffffu, c);
                int cnt = __popc(grp);
                bool isL = (lane == __ffs(grp) - 1);      // one leader per distinct code
                bool ok  = isL & (a < 20) & (b < 20);     // gaps contribute nothing
                if (s == 3) {                             // 25% -> atomic unit
                    if (ok) atomicAdd(&ha[c], cnt);
                } else {                                  // 75% -> plain crossbar RMW
                    if (ok) h[c] += cnt;                  // distinct addrs within batch
                }
            }
        }
    }
    __syncwarp();

    // Integer marginals over the 20x20 non-gap block, H = hist + hista
    int rs = 0, cs = 0;
    if (lane < 20) {
#pragma unroll
        for (int b = 0; b < 20; b++) {
            rs += h[lane * 21 + b] + ha[lane * 21 + b];
            cs += h[b * 21 + lane] + ha[b * 21 + lane];
        }
        slra[wid][lane] = lut[rs];
        slcb[wid][lane] = lut[cs];
    }
    int tv = (lane < 20) ? rs : 0;
#pragma unroll
    for (int off = 16; off; off >>= 1) tv += __shfl_xor_sync(0xffffffffu, tv, off);
    int tot = tv;
    __syncwarp();

    int tots = (tot > 0) ? tot : 1;
    float lt = lut[tots];
    float acc = 0.0f;
    for (int c = lane; c < 400; c += 32) {
        int a = (c * 3277) >> 16;       // c / 20 for c < 400
        int b = c - a * 20;
        int idx = a * 21 + b;
        int H = h[idx] + ha[idx];
        if (H > 0)
            acc += (float)H * (lut[H] - slra[wid][a] - slcb[wid][b] + lt);
    }
#pragma unroll
    for (int off = 16; off; off >>= 1) acc += __shfl_xor_sync(0xffffffffu, acc, off);

    if (lane == 0) {
        float mi = (tot > 0) ? acc / (float)tots : 0.0f;
        mi_out[i * SEQ_LEN + j] = mi;
        mi_out[j * SEQ_LEN + i] = mi;
    }
}

// ---------------------------------------------------------------------------
// Launch graph:
//   0 : pack(+zero MI) ── mi ── wait(e_join)
//   s1: (from t=0) count ── pssm ── e_join        (fully independent of pack)
// ---------------------------------------------------------------------------
extern "C" void kernel_launch(void* const* d_in, const int* in_sizes, int n_in,
                              void* d_out, int out_size) {
    const int*   msa = (const int*)d_in[0];
    const float* pc  = (const float*)d_in[1];
    float*       out = (float*)d_out;

    static cudaStream_t s1;
    static cudaEvent_t e_start, e_join;
    static bool init = false;
    if (!init) {
        cudaStreamCreateWithFlags(&s1, cudaStreamNonBlocking);
        cudaEventCreateWithFlags(&e_start, cudaEventDisableTiming);
        cudaEventCreateWithFlags(&e_join, cudaEventDisableTiming);
        init = true;
    }

    cudaEventRecord(e_start, 0);

    // Side stream: counts + pssm/conservation, concurrent with pack + mi
    cudaStreamWaitEvent(s1, e_start, 0);
    count_kernel<<<dim3(16, 4), 256, 0, s1>>>(msa);
    pssm_kernel<<<64, 256, 0, s1>>>(out, pc);
    cudaEventRecord(e_join, s1);

    // Main stream: pack (mi's only dependency) then the dominant mi kernel
    pack_kernel<<<dim3(4, 64), 256>>>(msa, out);
    mi_kernel<<<(N_PAIRS + 7) / 8, 256>>>(out + OUT_MI);
    cudaStreamWaitEvent(0, e_join, 0);
}

// round 7
// speedup vs baseline: 3.8098x; 3.8098x over previous
#include <cuda_runtime.h>
#include <cuda_bf16.h>
#include <math.h>
#include <stdint.h>

#define N_SEQS   2048
#define SEQ_LEN  512
#define N_AA     20
#define M_MI     100
#define N_PAIRS  4950                    // 100*99/2 upper triangle
#define OUT_PSSM 0
#define OUT_CONS (SEQ_LEN * N_AA)        // 10240
#define OUT_MI   (OUT_CONS + SEQ_LEN)    // 10752
#define OUT_TOTAL (OUT_MI + SEQ_LEN * SEQ_LEN)  // 272896

// Scratch (no dynamic allocation allowed)
__device__ unsigned char g_colpack[128 * N_SEQS];    // column-major int8 msa[:, :128] (100 used)

// ---------------------------------------------------------------------------
// Pack columns 0..99 into int8 column-major (coalesced reads, lane = column)
// AND zero the MI output region. grid (4, 64) x 256 = 65536 threads:
// one float4 of the MI region + one uint32 pack store per thread. Reads 1MB.
// ---------------------------------------------------------------------------
__global__ __launch_bounds__(256) void pack_kernel(const int* __restrict__ msa,
                                                   float* __restrict__ out) {
    int tid = threadIdx.x, lane = tid & 31, w = tid >> 5;

    // Zero MI region (512*512 floats = 65536 float4)
    int gtid = (blockIdx.y * 4 + blockIdx.x) * 256 + tid;
    ((float4*)(out + OUT_MI))[gtid] = make_float4(0.f, 0.f, 0.f, 0.f);

    int col   = blockIdx.x * 32 + lane;          // 0..127 (stores only col<100)
    int rbase = blockIdx.y * 32 + w * 4;
    uint32_t p0 = 0;
#pragma unroll
    for (int s = 0; s < 4; s++)
        p0 |= (uint32_t)msa[(rbase + s) * SEQ_LEN + col] << (8 * s);
    if (col < M_MI)
        *(uint32_t*)&g_colpack[col * N_SEQS + rbase] = p0;
}

// ---------------------------------------------------------------------------
// Fused counts + PSSM + conservation in ONE kernel (runs hidden under mi on a
// side stream). grid 16 x 256: CTA bx owns 32 columns x all 2048 rows.
// Per-warp replica histograms (plain private smem RMW, no atomics), merge,
// then 8 warps compute pssm/entropy for 4 positions each (lane = amino acid).
// ---------------------------------------------------------------------------
__global__ __launch_bounds__(256) void count_pssm_kernel(const int* __restrict__ msa,
                                                         float* __restrict__ out,
                                                         const float* __restrict__ pc) {
    __shared__ int cnt[8][32][21];     // [warp][lane(col)][symbol]
    __shared__ int merged[32][21];
    int tid = threadIdx.x, lane = tid & 31, w = tid >> 5;
    for (int v = tid; v < 8 * 32 * 21; v += 256) ((int*)cnt)[v] = 0;
    __syncthreads();

    int col   = blockIdx.x * 32 + lane;
    int rbase = w * 256;
    int* my = cnt[w][lane];
#pragma unroll 8
    for (int s = 0; s < 256; s++) {
        int c = msa[(rbase + s) * SEQ_LEN + col];   // coalesced 128B per warp
        my[c] += 1;                                  // private: plain RMW
    }
    __syncthreads();

    for (int v = tid; v < 32 * 21; v += 256) {
        int l = v / 21, c = v % 21;
        int s = 0;
#pragma unroll
        for (int ww = 0; ww < 8; ww++) s += cnt[ww][l][c];
        merged[l][c] = s;
    }
    __syncthreads();

    float pcount = 0.01f * pc[0];
    float inv_den = 1.0f / ((float)N_SEQS + pcount * 20.0f);

    // Warp w handles local positions w*4 .. w*4+3
#pragma unroll
    for (int pl = 0; pl < 4; pl++) {
        int lp = w * 4 + pl;
        int p  = blockIdx.x * 32 + lp;
        int ct = (lane < 20) ? merged[lp][lane] : 0;

        int t = ct;
#pragma unroll
        for (int off = 16; off; off >>= 1) t += __shfl_xor_sync(0xffffffffu, t, off);
        int total = t;

        float tinv = 1.0f / fmaxf((float)total, 1.0f);
        float ent = 0.0f;
        if (lane < 20) {
            float freq = ((float)ct + pcount) * inv_den;
            out[OUT_PSSM + p * 20 + lane] = logf(freq * 20.0f + 1e-10f);
            float f = (float)ct * tinv;
            ent = -f * log2f(f + 1e-10f);
        }
#pragma unroll
        for (int off = 16; off; off >>= 1) ent += __shfl_xor_sync(0xffffffffu, ent, off);
        if (lane == 0)
            out[OUT_CONS + p] = (total > 0) ? (1.0f - ent * (1.0f / 4.321928094887362f)) : 0.0f;
    }
}

// ---------------------------------------------------------------------------
// MI: one warp per (i<j) pair — the measured-at-the-ATOMS-floor Round-3
// version, verbatim. 400-bin smem histogram; gap events predicated out.
// Integer log2 LUT epilogue (no MUFU in the hot path).
// ---------------------------------------------------------------------------
__global__ __launch_bounds__(256) void mi_kernel(float* __restrict__ mi_out) {
    __shared__ int   hist[8][400];
    __shared__ float lut[2049];       // log2(0..2048)
    __shared__ float slra[8][20];
    __shared__ float slcb[8][20];

    int tid = threadIdx.x, wid = tid >> 5, lane = tid & 31;
    for (int v = tid; v < 2049; v += 256) lut[v] = log2f((float)v);
    __syncthreads();

    int pid = blockIdx.x * 8 + wid;
    if (pid >= N_PAIRS) return;

    // Decode upper-triangle pair index -> (i, j), i < j; T(i) = i*(199-i)/2
    float d = sqrtf(39601.0f - 8.0f * (float)pid);
    int i = (int)((199.0f - d) * 0.5f);
    if (i < 0) i = 0;
    if (i > 98) i = 98;
    while ((((i + 1) * (199 - (i + 1))) >> 1) <= pid) ++i;
    while (((i * (199 - i)) >> 1) > pid) --i;
    int j = pid - ((i * (199 - i)) >> 1) + i + 1;

    int* h = hist[wid];
    for (int v = lane; v < 400; v += 32) h[v] = 0;
    __syncwarp();

    const uint4* ca = (const uint4*)(g_colpack + i * N_SEQS);
    const uint4* cb = (const uint4*)(g_colpack + j * N_SEQS);
#pragma unroll
    for (int it = 0; it < 4; it++) {                // 4 x LDG.128 per operand
        uint4 va = ca[lane + 32 * it];
        uint4 vb = cb[lane + 32 * it];
        const uint32_t wa_[4] = {va.x, va.y, va.z, va.w};
        const uint32_t wb_[4] = {vb.x, vb.y, vb.z, vb.w};
#pragma unroll
        for (int q = 0; q < 4; q++) {
            uint32_t wa = wa_[q], wb = wb_[q];
#pragma unroll
            for (int s = 0; s < 4; s++) {
                int a = (wa >> (8 * s)) & 255;
                int b = (wb >> (8 * s)) & 255;
                if (a < 20 && b < 20)
                    atomicAdd(&h[a * 20 + b], 1);
            }
        }
    }
    __syncwarp();

    // Integer marginals over the 20x20 block
    int rs = 0, cs = 0;
    if (lane < 20) {
#pragma unroll
        for (int b = 0; b < 20; b++) { rs += h[lane * 20 + b]; cs += h[b * 20 + lane]; }
        slra[wid][lane] = lut[rs];
        slcb[wid][lane] = lut[cs];
    }
    int tv = (lane < 20) ? rs : 0;
#pragma unroll
    for (int off = 16; off; off >>= 1) tv += __shfl_xor_sync(0xffffffffu, tv, off);
    int tot = tv;
    __syncwarp();

    int tots = (tot > 0) ? tot : 1;
    float lt = lut[tots];
    float acc = 0.0f;
    for (int c = lane; c < 400; c += 32) {
        int H = h[c];
        if (H > 0) {
            int a = (c * 3277) >> 16;   // c / 20 for c < 400
            int b = c - a * 20;
            acc += (float)H * (lut[H] - slra[wid][a] - slcb[wid][b] + lt);
        }
    }
#pragma unroll
    for (int off = 16; off; off >>= 1) acc += __shfl_xor_sync(0xffffffffu, acc, off);

    if (lane == 0) {
        float mi = (tot > 0) ? acc / (float)tots : 0.0f;
        mi_out[i * SEQ_LEN + j] = mi;
        mi_out[j * SEQ_LEN + i] = mi;
    }
}

// ---------------------------------------------------------------------------
// Launch graph (critical path = pack -> mi):
//   0 : e_start ── pack(+zero MI) ── mi ── wait(e_join)
//   s1: wait(e_start) ── count_pssm ── e_join      (hidden under pack+mi)
// ---------------------------------------------------------------------------
extern "C" void kernel_launch(void* const* d_in, const int* in_sizes, int n_in,
                              void* d_out, int out_size) {
    const int*   msa = (const int*)d_in[0];
    const float* pc  = (const float*)d_in[1];
    float*       out = (float*)d_out;

    static cudaStream_t s1;
    static cudaEvent_t e_start, e_join;
    static bool init = false;
    if (!init) {
        cudaStreamCreateWithFlags(&s1, cudaStreamNonBlocking);
        cudaEventCreateWithFlags(&e_start, cudaEventDisableTiming);
        cudaEventCreateWithFlags(&e_join, cudaEventDisableTiming);
        init = true;
    }

    cudaEventRecord(e_start, 0);

    // Side stream: fused counts + pssm + conservation, concurrent with pack+mi
    cudaStreamWaitEvent(s1, e_start, 0);
    count_pssm_kernel<<<16, 256, 0, s1>>>(msa, out, pc);
    cudaEventRecord(e_join, s1);

    // Main stream: pack (mi's only dependency), then the dominant mi kernel
    pack_kernel<<<dim3(4, 64), 256>>>(msa, out);
    mi_kernel<<<(N_PAIRS + 7) / 8, 256>>>(out + OUT_MI);
    cudaStreamWaitEvent(0, e_join, 0);
}

// round 8
// speedup vs baseline: 4.1773x; 1.0965x over previous
#include <cuda_runtime.h>
#include <cuda_bf16.h>
#include <math.h>
#include <stdint.h>

#define N_SEQS   2048
#define SEQ_LEN  512
#define N_AA     20
#define M_MI     100
#define N_PAIRS  4950                    // 100*99/2 upper triangle
#define OUT_PSSM 0
#define OUT_CONS (SEQ_LEN * N_AA)        // 10240
#define OUT_MI   (OUT_CONS + SEQ_LEN)    // 10752
#define OUT_TOTAL (OUT_MI + SEQ_LEN * SEQ_LEN)  // 272896

// Scratch (no dynamic allocation allowed)
__device__ unsigned char g_colpack[128 * N_SEQS];    // column-major int8 msa[:, :128] (100 used)
__device__ int           g_part[16][SEQ_LEN][21];    // count partials (plain stores, no zeroing)

// ---------------------------------------------------------------------------
// Pack columns 0..99 into int8 column-major (coalesced reads, lane = column)
// AND zero the MI output region. grid (4, 64) x 256 = 65536 threads:
// one float4 of the MI region + one uint32 pack store per thread. Reads 1MB.
// ---------------------------------------------------------------------------
__global__ __launch_bounds__(256) void pack_kernel(const int* __restrict__ msa,
                                                   float* __restrict__ out) {
    int tid = threadIdx.x, lane = tid & 31, w = tid >> 5;

    // Zero MI region (512*512 floats = 65536 float4)
    int gtid = (blockIdx.y * 4 + blockIdx.x) * 256 + tid;
    ((float4*)(out + OUT_MI))[gtid] = make_float4(0.f, 0.f, 0.f, 0.f);

    int col   = blockIdx.x * 32 + lane;          // 0..127 (stores only col<100)
    int rbase = blockIdx.y * 32 + w * 4;
    uint32_t p0 = 0;
#pragma unroll
    for (int s = 0; s < 4; s++)
        p0 |= (uint32_t)msa[(rbase + s) * SEQ_LEN + col] << (8 * s);
    if (col < M_MI)
        *(uint32_t*)&g_colpack[col * N_SEQS + rbase] = p0;
}

// ---------------------------------------------------------------------------
// Per-position AA counts -> 16 PARTIALS via plain stores (no atomics, no
// pre-zero, no inter-kernel dependency). grid (16, 16) x 256: CTA covers
// 32 cols x 128 rows; per-warp replica histograms -> private smem RMW.
// ---------------------------------------------------------------------------
__global__ __launch_bounds__(256) void count_kernel(const int* __restrict__ msa) {
    __shared__ int cnt[8][32][21];     // [warp][lane(col)][symbol]
    int tid = threadIdx.x, lane = tid & 31, w = tid >> 5;
    for (int v = tid; v < 8 * 32 * 21; v += 256) ((int*)cnt)[v] = 0;
    __syncthreads();

    int col   = blockIdx.x * 32 + lane;
    int rbase = blockIdx.y * 128 + w * 16;
    int* my = cnt[w][lane];
#pragma unroll
    for (int s = 0; s < 16; s++) {
        int c = msa[(rbase + s) * SEQ_LEN + col];   // coalesced 128B per warp
        my[c] += 1;                                  // private: plain RMW
    }
    __syncthreads();

    for (int v = tid; v < 32 * 21; v += 256) {
        int l = v / 21, c = v % 21;
        int s = 0;
#pragma unroll
        for (int ww = 0; ww < 8; ww++) s += cnt[ww][l][c];
        g_part[blockIdx.y][blockIdx.x * 32 + l][c] = s;   // plain store
    }
}

// ---------------------------------------------------------------------------
// PSSM + conservation: one warp per position (lane = amino acid); sums the
// 16 count partials. 64 CTAs x 256.
// ---------------------------------------------------------------------------
__global__ __launch_bounds__(256) void pssm_kernel(float* __restrict__ out, const float* __restrict__ pc) {
    int gtid = blockIdx.x * blockDim.x + threadIdx.x;
    int p = gtid >> 5, lane = gtid & 31;
    if (p >= SEQ_LEN) return;

    int ct = 0;
    if (lane < 20) {
#pragma unroll
        for (int k = 0; k < 16; k++) ct += g_part[k][p][lane];
    }

    int t = ct;
#pragma unroll
    for (int off = 16; off; off >>= 1) t += __shfl_xor_sync(0xffffffffu, t, off);
    int total = t;

    float pcount = 0.01f * pc[0];
    float inv_den = 1.0f / ((float)N_SEQS + pcount * 20.0f);
    float tinv = 1.0f / fmaxf((float)total, 1.0f);

    float ent = 0.0f;
    if (lane < 20) {
        float freq = ((float)ct + pcount) * inv_den;
        out[OUT_PSSM + p * 20 + lane] = logf(freq * 20.0f + 1e-10f);
        float f = (float)ct * tinv;
        ent = -f * log2f(f + 1e-10f);
    }
#pragma unroll
    for (int off = 16; off; off >>= 1) ent += __shfl_xor_sync(0xffffffffu, ent, off);
    if (lane == 0)
        out[OUT_CONS + p] = (total > 0) ? (1.0f - ent * (1.0f / 4.321928094887362f)) : 0.0f;
}

// ---------------------------------------------------------------------------
// MI: one warp per (i<j) pair — measured at the smem-ATOMS floor (14.66us).
// 400-bin smem histogram; gap events predicated out. Integer log2 LUT
// epilogue (no MUFU in the hot path).
// ---------------------------------------------------------------------------
__global__ __launch_bounds__(256) void mi_kernel(float* __restrict__ mi_out) {
    __shared__ int   hist[8][400];
    __shared__ float lut[2049];       // log2(0..2048)
    __shared__ float slra[8][20];
    __shared__ float slcb[8][20];

    int tid = threadIdx.x, wid = tid >> 5, lane = tid & 31;
    for (int v = tid; v < 2049; v += 256) lut[v] = log2f((float)v);
    __syncthreads();

    int pid = blockIdx.x * 8 + wid;
    if (pid >= N_PAIRS) return;

    // Decode upper-triangle pair index -> (i, j), i < j; T(i) = i*(199-i)/2
    float d = sqrtf(39601.0f - 8.0f * (float)pid);
    int i = (int)((199.0f - d) * 0.5f);
    if (i < 0) i = 0;
    if (i > 98) i = 98;
    while ((((i + 1) * (199 - (i + 1))) >> 1) <= pid) ++i;
    while (((i * (199 - i)) >> 1) > pid) --i;
    int j = pid - ((i * (199 - i)) >> 1) + i + 1;

    int* h = hist[wid];
    for (int v = lane; v < 400; v += 32) h[v] = 0;
    __syncwarp();

    const uint4* ca = (const uint4*)(g_colpack + i * N_SEQS);
    const uint4* cb = (const uint4*)(g_colpack + j * N_SEQS);
#pragma unroll
    for (int it = 0; it < 4; it++) {                // 4 x LDG.128 per operand
        uint4 va = ca[lane + 32 * it];
        uint4 vb = cb[lane + 32 * it];
        const uint32_t wa_[4] = {va.x, va.y, va.z, va.w};
        const uint32_t wb_[4] = {vb.x, vb.y, vb.z, vb.w};
#pragma unroll
        for (int q = 0; q < 4; q++) {
            uint32_t wa = wa_[q], wb = wb_[q];
#pragma unroll
            for (int s = 0; s < 4; s++) {
                int a = (wa >> (8 * s)) & 255;
                int b = (wb >> (8 * s)) & 255;
                if (a < 20 && b < 20)
                    atomicAdd(&h[a * 20 + b], 1);
            }
        }
    }
    __syncwarp();

    // Integer marginals over the 20x20 block
    int rs = 0, cs = 0;
    if (lane < 20) {
#pragma unroll
        for (int b = 0; b < 20; b++) { rs += h[lane * 20 + b]; cs += h[b * 20 + lane]; }
        slra[wid][lane] = lut[rs];
        slcb[wid][lane] = lut[cs];
    }
    int tv = (lane < 20) ? rs : 0;
#pragma unroll
    for (int off = 16; off; off >>= 1) tv += __shfl_xor_sync(0xffffffffu, tv, off);
    int tot = tv;
    __syncwarp();

    int tots = (tot > 0) ? tot : 1;
    float lt = lut[tots];
    float acc = 0.0f;
    for (int c = lane; c < 400; c += 32) {
        int H = h[c];
        if (H > 0) {
            int a = (c * 3277) >> 16;   // c / 20 for c < 400
            int b = c - a * 20;
            acc += (float)H * (lut[H] - slra[wid][a] - slcb[wid][b] + lt);
        }
    }
#pragma unroll
    for (int off = 16; off; off >>= 1) acc += __shfl_xor_sync(0xffffffffu, acc, off);

    if (lane == 0) {
        float mi = (tot > 0) ? acc / (float)tots : 0.0f;
        mi_out[i * SEQ_LEN + j] = mi;
        mi_out[j * SEQ_LEN + i] = mi;
    }
}

// ---------------------------------------------------------------------------
// Launch graph (critical path = pack -> mi):
//   0 : e_start ── pack(+zero MI) ── mi ── wait(e_join)
//   s1: wait(e_start) ── count ── pssm ── e_join   (hidden under pack+mi)
// ---------------------------------------------------------------------------
extern "C" void kernel_launch(void* const* d_in, const int* in_sizes, int n_in,
                              void* d_out, int out_size) {
    const int*   msa = (const int*)d_in[0];
    const float* pc  = (const float*)d_in[1];
    float*       out = (float*)d_out;

    static cudaStream_t s1;
    static cudaEvent_t e_start, e_join;
    static bool init = false;
    if (!init) {
        cudaStreamCreateWithFlags(&s1, cudaStreamNonBlocking);
        cudaEventCreateWithFlags(&e_start, cudaEventDisableTiming);
        cudaEventCreateWithFlags(&e_join, cudaEventDisableTiming);
        init = true;
    }

    cudaEventRecord(e_start, 0);

    // Side stream: counts + pssm/conservation, concurrent with pack + mi
    cudaStreamWaitEvent(s1, e_start, 0);
    count_kernel<<<dim3(16, 16), 256, 0, s1>>>(msa);
    pssm_kernel<<<64, 256, 0, s1>>>(out, pc);
    cudaEventRecord(e_join, s1);

    // Main stream: pack (mi's only dependency), then the dominant mi kernel
    pack_kernel<<<dim3(4, 64), 256>>>(msa, out);
    mi_kernel<<<(N_PAIRS + 7) / 8, 256>>>(out + OUT_MI);
    cudaStreamWaitEvent(0, e_join, 0);
}

// round 9
// speedup vs baseline: 4.5730x; 1.0947x over previous
#include <cuda_runtime.h>
#include <cuda_bf16.h>
#include <math.h>
#include <stdint.h>

#define N_SEQS   2048
#define SEQ_LEN  512
#define N_AA     20
#define M_MI     100
#define N_PAIRS  4950                    // 100*99/2 upper triangle
#define OUT_PSSM 0
#define OUT_CONS (SEQ_LEN * N_AA)        // 10240
#define OUT_MI   (OUT_CONS + SEQ_LEN)    // 10752
#define OUT_TOTAL (OUT_MI + SEQ_LEN * SEQ_LEN)  // 272896

// Scratch (no dynamic allocation allowed)
__device__ unsigned char g_colpack[128 * N_SEQS];    // column-major int8 msa[:, :128] (100 used)
__device__ int           g_part[16][SEQ_LEN][21];    // count partials (plain stores, no zeroing)

// ---------------------------------------------------------------------------
// FUSED PREP: one pass over msa does everything except MI and the final pssm:
//   (a) per-position AA counts -> per-warp replica smem hists -> g_part stores
//   (b) int8 column pack for MI columns (cols < 100), one uint4 store/thread
//   (c) zero the MI output region (one float4 per thread, 256 CTAs x 256 = all)
// grid (16, 16) x 256: CTA covers 32 cols x 128 rows; thread handles 16 rows
// of one column (coalesced 128B per warp per row). No atomics anywhere.
// ---------------------------------------------------------------------------
__global__ __launch_bounds__(256) void prep_kernel(const int* __restrict__ msa,
                                                   float* __restrict__ out) {
    __shared__ int cnt[8][32][21];     // [warp][lane(col)][symbol]
    int tid = threadIdx.x, lane = tid & 31, w = tid >> 5;
    for (int v = tid; v < 8 * 32 * 21; v += 256) ((int*)cnt)[v] = 0;

    // (c) zero MI region: 512*512 floats = 65536 float4 == 256 CTAs * 256 thr
    int gz = (blockIdx.y * 16 + blockIdx.x) * 256 + tid;
    ((float4*)(out + OUT_MI))[gz] = make_float4(0.f, 0.f, 0.f, 0.f);
    __syncthreads();

    int col   = blockIdx.x * 32 + lane;
    int rbase = blockIdx.y * 128 + w * 16;
    int* my = cnt[w][lane];

    uint32_t pk0 = 0, pk1 = 0, pk2 = 0, pk3 = 0;
#pragma unroll
    for (int s = 0; s < 16; s++) {
        int c = msa[(rbase + s) * SEQ_LEN + col];   // coalesced 128B per warp
        my[c] += 1;                                  // private replica: plain RMW
        uint32_t cc = (uint32_t)c << (8 * (s & 3));
        if ((s >> 2) == 0) pk0 |= cc;
        else if ((s >> 2) == 1) pk1 |= cc;
        else if ((s >> 2) == 2) pk2 |= cc;
        else pk3 |= cc;
    }
    if (col < M_MI)                                  // (b) pack store, 16B aligned
        *(uint4*)&g_colpack[col * N_SEQS + rbase] = make_uint4(pk0, pk1, pk2, pk3);
    __syncthreads();

    // (a) merge 8 replicas -> partial store (no atomics, no pre-zero needed)
    for (int v = tid; v < 32 * 21; v += 256) {
        int l = v / 21, c = v % 21;
        int s = 0;
#pragma unroll
        for (int ww = 0; ww < 8; ww++) s += cnt[ww][l][c];
        g_part[blockIdx.y][blockIdx.x * 32 + l][c] = s;
    }
}

// ---------------------------------------------------------------------------
// PSSM + conservation: one warp per position (lane = amino acid); sums the
// 16 count partials. 64 CTAs x 256.
// ---------------------------------------------------------------------------
__global__ __launch_bounds__(256) void pssm_kernel(float* __restrict__ out, const float* __restrict__ pc) {
    int gtid = blockIdx.x * blockDim.x + threadIdx.x;
    int p = gtid >> 5, lane = gtid & 31;
    if (p >= SEQ_LEN) return;

    int ct = 0;
    if (lane < 20) {
#pragma unroll
        for (int k = 0; k < 16; k++) ct += g_part[k][p][lane];
    }

    int t = ct;
#pragma unroll
    for (int off = 16; off; off >>= 1) t += __shfl_xor_sync(0xffffffffu, t, off);
    int total = t;

    float pcount = 0.01f * pc[0];
    float inv_den = 1.0f / ((float)N_SEQS + pcount * 20.0f);
    float tinv = 1.0f / fmaxf((float)total, 1.0f);

    float ent = 0.0f;
    if (lane < 20) {
        float freq = ((float)ct + pcount) * inv_den;
        out[OUT_PSSM + p * 20 + lane] = logf(freq * 20.0f + 1e-10f);
        float f = (float)ct * tinv;
        ent = -f * log2f(f + 1e-10f);
    }
#pragma unroll
    for (int off = 16; off; off >>= 1) ent += __shfl_xor_sync(0xffffffffu, ent, off);
    if (lane == 0)
        out[OUT_CONS + p] = (total > 0) ? (1.0f - ent * (1.0f / 4.321928094887362f)) : 0.0f;
}

// ---------------------------------------------------------------------------
// MI: one warp per (i<j) pair — measured at the smem-ATOMS floor (14.7us,
// reproduced 3x). 400-bin smem histogram; gap events predicated out.
// Integer log2 LUT epilogue (no MUFU in the hot path). DO NOT TOUCH.
// ---------------------------------------------------------------------------
__global__ __launch_bounds__(256) void mi_kernel(float* __restrict__ mi_out) {
    __shared__ int   hist[8][400];
    __shared__ float lut[2049];       // log2(0..2048)
    __shared__ float slra[8][20];
    __shared__ float slcb[8][20];

    int tid = threadIdx.x, wid = tid >> 5, lane = tid & 31;
    for (int v = tid; v < 2049; v += 256) lut[v] = log2f((float)v);
    __syncthreads();

    int pid = blockIdx.x * 8 + wid;
    if (pid >= N_PAIRS) return;

    // Decode upper-triangle pair index -> (i, j), i < j; T(i) = i*(199-i)/2
    float d = sqrtf(39601.0f - 8.0f * (float)pid);
    int i = (int)((199.0f - d) * 0.5f);
    if (i < 0) i = 0;
    if (i > 98) i = 98;
    while ((((i + 1) * (199 - (i + 1))) >> 1) <= pid) ++i;
    while (((i * (199 - i)) >> 1) > pid) --i;
    int j = pid - ((i * (199 - i)) >> 1) + i + 1;

    int* h = hist[wid];
    for (int v = lane; v < 400; v += 32) h[v] = 0;
    __syncwarp();

    const uint4* ca = (const uint4*)(g_colpack + i * N_SEQS);
    const uint4* cb = (const uint4*)(g_colpack + j * N_SEQS);
#pragma unroll
    for (int it = 0; it < 4; it++) {                // 4 x LDG.128 per operand
        uint4 va = ca[lane + 32 * it];
        uint4 vb = cb[lane + 32 * it];
        const uint32_t wa_[4] = {va.x, va.y, va.z, va.w};
        const uint32_t wb_[4] = {vb.x, vb.y, vb.z, vb.w};
#pragma unroll
        for (int q = 0; q < 4; q++) {
            uint32_t wa = wa_[q], wb = wb_[q];
#pragma unroll
            for (int s = 0; s < 4; s++) {
                int a = (wa >> (8 * s)) & 255;
                int b = (wb >> (8 * s)) & 255;
                if (a < 20 && b < 20)
                    atomicAdd(&h[a * 20 + b], 1);
            }
        }
    }
    __syncwarp();

    // Integer marginals over the 20x20 block
    int rs = 0, cs = 0;
    if (lane < 20) {
#pragma unroll
        for (int b = 0; b < 20; b++) { rs += h[lane * 20 + b]; cs += h[b * 20 + lane]; }
        slra[wid][lane] = lut[rs];
        slcb[wid][lane] = lut[cs];
    }
    int tv = (lane < 20) ? rs : 0;
#pragma unroll
    for (int off = 16; off; off >>= 1) tv += __shfl_xor_sync(0xffffffffu, tv, off);
    int tot = tv;
    __syncwarp();

    int tots = (tot > 0) ? tot : 1;
    float lt = lut[tots];
    float acc = 0.0f;
    for (int c = lane; c < 400; c += 32) {
        int H = h[c];
        if (H > 0) {
            int a = (c * 3277) >> 16;   // c / 20 for c < 400
            int b = c - a * 20;
            acc += (float)H * (lut[H] - slra[wid][a] - slcb[wid][b] + lt);
        }
    }
#pragma unroll
    for (int off = 16; off; off >>= 1) acc += __shfl_xor_sync(0xffffffffu, acc, off);

    if (lane == 0) {
        float mi = (tot > 0) ? acc / (float)tots : 0.0f;
        mi_out[i * SEQ_LEN + j] = mi;
        mi_out[j * SEQ_LEN + i] = mi;
    }
}

// ---------------------------------------------------------------------------
// Launch: SINGLE stream, 3 nodes, no events, no memsets, no side streams.
// (Cross-stream fork/join event nodes measured +4-5us of graph overhead —
//  more than the ~2.7us of work they hid.)
// ---------------------------------------------------------------------------
extern "C" void kernel_launch(void* const* d_in, const int* in_sizes, int n_in,
                              void* d_out, int out_size) {
    const int*   msa = (const int*)d_in[0];
    const float* pc  = (const float*)d_in[1];
    float*       out = (float*)d_out;

    prep_kernel<<<dim3(16, 16), 256>>>(msa, out);   // counts + pack + zero MI
    pssm_kernel<<<64, 256>>>(out, pc);              // pssm + conservation
    mi_kernel<<<(N_PAIRS + 7) / 8, 256>>>(out + OUT_MI);  // dominant MI
}